// round 7
// baseline (speedup 1.0000x reference)
#include <cuda_runtime.h>

// ---------------- problem dims (fixed by the dataset) ----------------
#define BATCH   2
#define C_IN    256
#define HH      40
#define WW      40
#define CMID    64     // compressed channels
#define CK      100    // k2 * S^2 encoder output channels
#define KK      25     // k2
#define HPAD    44     // xT padded (halo 2)
#define CPH     42     // comp padded (halo 1)

typedef unsigned long long u64;

__device__ __forceinline__ u64 dup2f(float x) {
    u64 r; asm("mov.b64 %0,{%1,%1};" : "=l"(r) : "f"(x)); return r;
}
__device__ __forceinline__ void fma2(u64& d, u64 a, u64 b) {
    asm("fma.rn.f32x2 %0,%1,%2,%0;" : "+l"(d) : "l"(a), "l"(b));
}

// ---------------- scratch (zero-initialized at module load; halos stay 0) ----------------
__device__ __align__(16) float g_xT  [BATCH * HPAD * HPAD * C_IN];   // x NHWC, 2-px zero halo
__device__ __align__(16) float g_comp[BATCH * CPH  * CPH  * CMID];   // compressed NHWC, 1-px halo
__device__ __align__(16) float g_kern[BATCH * HH * WW * CK];         // encoder conv out, NHWC
__device__ __align__(16) float g_wt  [2 * 9 * CMID * 50];            // w_enc [half][tap][ci][50]

// ---------------- mega kernel 1: A-GEMM (0..199) + x transpose (200..599) + w_enc prep (600..1049)
#define AW_STRIDE 68
#define AX_STRIDE 20

__global__ void __launch_bounds__(128) megaA(const float* __restrict__ x,
                                             const float* __restrict__ wcomp,
                                             const float* __restrict__ wenc) {
    __shared__ float sm[64 * AW_STRIDE + 64 * AX_STRIDE];
    const int t   = threadIdx.x;
    const int blk = blockIdx.x;

    if (blk < 200) {
        // ---- 1x1 compress GEMM: 16 px x 64 outputs, K chunked by 64 ----
        float* w_s = sm;                    // [c_local][o] stride 68
        float* x_s = sm + 64 * AW_STRIDE;   // [c_local][px] stride 20

        const int g = blk * 16;             // global pixel (incl batch), 16-aligned
        const int b = g / (HH * WW);
        const int p = g % (HH * WW);

        const int px = t & 15;
        const int o0 = (t >> 4) << 3;       // 8 consecutive outputs

        u64 acc0 = 0, acc1 = 0, acc2 = 0, acc3 = 0;

        for (int c0 = 0; c0 < C_IN; c0 += 64) {
            __syncthreads();
            // transpose-load weights chunk: wcomp[o][c0+cl] -> w_s[cl][o]
            #pragma unroll
            for (int r = 0; r < 8; r++) {
                int f = t + r * 128;
                int o = f >> 4, cl4 = f & 15;
                float4 w4 = *(const float4*)&wcomp[o * C_IN + c0 + cl4 * 4];
                w_s[(cl4 * 4 + 0) * AW_STRIDE + o] = w4.x;
                w_s[(cl4 * 4 + 1) * AW_STRIDE + o] = w4.y;
                w_s[(cl4 * 4 + 2) * AW_STRIDE + o] = w4.z;
                w_s[(cl4 * 4 + 3) * AW_STRIDE + o] = w4.w;
            }
            // x chunk: 64 rows x 16 px
            #pragma unroll
            for (int r = 0; r < 2; r++) {
                int f = t + r * 128;
                int row = f >> 2, col4 = f & 3;
                *(float4*)&x_s[row * AX_STRIDE + col4 * 4] =
                    *(const float4*)&x[((size_t)(b * C_IN) + c0 + row) * (HH * WW) + p + col4 * 4];
            }
            __syncthreads();
            #pragma unroll 8
            for (int c = 0; c < 64; c++) {
                u64 xx = dup2f(x_s[c * AX_STRIDE + px]);
                ulonglong2 wA = *(const ulonglong2*)&w_s[c * AW_STRIDE + o0];
                ulonglong2 wB = *(const ulonglong2*)&w_s[c * AW_STRIDE + o0 + 4];
                fma2(acc0, xx, wA.x); fma2(acc1, xx, wA.y);
                fma2(acc2, xx, wB.x); fma2(acc3, xx, wB.y);
            }
        }

        const int pix = p + px;
        const int hs = pix / WW, ws = pix % WW;
        float* dst = &g_comp[((size_t)(b * CPH + hs + 1) * CPH + (ws + 1)) * CMID + o0];
        *(ulonglong2*)(dst)     = make_ulonglong2(acc0, acc1);
        *(ulonglong2*)(dst + 4) = make_ulonglong2(acc2, acc3);
    } else if (blk < 600) {
        // ---- x transpose: 32 px x 64 ch tile through smem ----
        float* s = sm;                      // [64][33]
        const int tb = blk - 200;
        const int pg = (tb % 100) * 32;
        const int c0 = (tb / 100) * 64;
        const int b  = pg / (HH * WW);
        const int p0 = pg % (HH * WW);
        #pragma unroll
        for (int r = 0; r < 16; r++) {
            int idx = t + r * 128;
            int cl = idx >> 5, pl = idx & 31;
            s[cl * 33 + pl] = x[((size_t)(b * C_IN) + c0 + cl) * (HH * WW) + p0 + pl];
        }
        __syncthreads();
        #pragma unroll
        for (int r = 0; r < 16; r++) {
            int idx = t + r * 128;
            int pl = idx >> 6, cl = idx & 63;
            int px = p0 + pl;
            int hs = px / WW, ws = px % WW;
            g_xT[((size_t)(b * HPAD + hs + 2) * HPAD + (ws + 2)) * C_IN + c0 + cl] =
                s[cl * 33 + pl];
        }
    } else {
        // ---- w_enc prep: g_wt[h][tap][ci][ol] = wenc[50h+ol][ci][tap] ----
        int j = (blk - 600) * 128 + t;
        if (j < 57600) {
            int h   = j / 28800;
            int r   = j % 28800;
            int tap = r / 3200;
            int r2  = r % 3200;
            int ci  = r2 / 50;
            int ol  = r2 % 50;
            g_wt[j] = wenc[(50 * h + ol) * (CMID * 9) + ci * 9 + tap];
        }
    }
}

// ---------------- stage B: 3x3 encoder conv (64 -> 100 ch) ----------------
// 320 blocks = b(2) x ohalf(2) x rowpair(20) x colseg(4); 128 threads.
// comp tile in smem (12.7KB); weights streamed from L2 via unrolled LDG.
#define W_HALF    28800                     // 9*64*50 floats
#define CS_STRIDE 66

__global__ void __launch_bounds__(128) stageB_encoder() {
    __shared__ float comp_s[48 * CS_STRIDE];

    const int t    = threadIdx.x;
    const int blk  = blockIdx.x;
    const int b    = blk / 160;
    const int rem  = blk % 160;
    const int h    = rem / 80;              // output-channel half
    const int rem2 = rem % 80;
    const int r0   = (rem2 / 4) * 2;        // output rows r0, r0+1
    const int cs0  = (rem2 % 4) * 10;       // output cols cs0..cs0+9

    #pragma unroll
    for (int r = 0; r < 12; r++) {
        int i  = t + r * 128;
        int px = i >> 5, c2 = i & 31;
        int dr = px / 12, dc = px % 12;
        *(float2*)&comp_s[px * CS_STRIDE + c2 * 2] =
            *(const float2*)&g_comp[((size_t)(b * CPH + r0 + dr) * CPH + cs0 + dc) * CMID + c2 * 2];
    }
    __syncthreads();

    const int og = t / 5;                   // 0..25 (active < 25)
    const int cp = t % 5;
    if (og >= 25) return;

    u64 a00 = 0, a01 = 0, a10 = 0, a11 = 0;
    const float* wt0 = &g_wt[h * W_HALF + og * 2];
    #pragma unroll
    for (int tap = 0; tap < 9; tap++) {
        const float* xb = &comp_s[((tap / 3) * 12 + 2 * cp + (tap % 3)) * CS_STRIDE];
        const float* wt = wt0 + tap * 3200;
        #pragma unroll 8
        for (int ci = 0; ci < CMID; ci += 2) {
            float2 x00 = *(const float2*)&xb[ci];
            float2 x01 = *(const float2*)&xb[CS_STRIDE + ci];
            float2 x10 = *(const float2*)&xb[12 * CS_STRIDE + ci];
            float2 x11 = *(const float2*)&xb[13 * CS_STRIDE + ci];
            u64 w0 = *(const u64*)&wt[ci * 50];
            u64 w1 = *(const u64*)&wt[ci * 50 + 50];
            fma2(a00, dup2f(x00.x), w0); fma2(a01, dup2f(x01.x), w0);
            fma2(a10, dup2f(x10.x), w0); fma2(a11, dup2f(x11.x), w0);
            fma2(a00, dup2f(x00.y), w1); fma2(a01, dup2f(x01.y), w1);
            fma2(a10, dup2f(x10.y), w1); fma2(a11, dup2f(x11.y), w1);
        }
    }
    const int oc = h * 50 + og * 2;
    const int c0 = cs0 + 2 * cp;
    float* d00 = &g_kern[((size_t)(b * HH + r0) * WW + c0) * CK + oc];
    *(u64*)d00        = a00;
    *(u64*)(d00 + CK) = a01;
    float* d10 = d00 + WW * CK;
    *(u64*)d10        = a10;
    *(u64*)(d10 + CK) = a11;
}

// ---------------- stage C: sliding-window reassembly, coalesced stores ----------------
// 640 blocks x 256 threads: 5 source px per block (p0 = 5q, same hu/hsrc),
// thread = 1 channel. Window 5x9 loaded once; stores staged via smem.
#define ST_STRIDE 24

__global__ void __launch_bounds__(256) stageC_reassemble(float* __restrict__ out) {
    __shared__ float4 sk[5][KK];            // softmax weights per px
    __shared__ float  st[256 * ST_STRIDE];  // [ch][20+pad] output staging

    const int t   = threadIdx.x;
    const int blk = blockIdx.x;
    const int b   = blk / 320;
    const int p0  = (blk % 320) * 5;

    const int hu    = p0 / 20, pm0 = p0 % 20;
    const int hsrc  = p0 / WW, wsrc0 = p0 % WW;   // shared by all 5 px (wsrc_i = wsrc0+i)
    const int wid = t >> 5, lane = t & 31;

    // ---- window loads: 5 rows x 9 cols, all issued up front ----
    const float* xb = &g_xT[((size_t)(b * HPAD + hsrc) * HPAD + wsrc0) * C_IN + t];
    float xw[45];
    #pragma unroll
    for (int r = 0; r < 5; r++)
        #pragma unroll
        for (int c = 0; c < 9; c++)
            xw[r * 9 + c] = xb[(r * HPAD + c) * C_IN];

    // ---- 20 softmaxes (5 px x 4 subpx), 8 warps loop ----
    const int hc = hu >> 1, sh = hu & 1;
    for (int s = wid; s < 20; s += 8) {
        const int px = s >> 2, d = s & 3;
        const int wc = 2 * (pm0 + px) + (d >> 1), sw = d & 1;
        float v = -3.0e38f;
        if (lane < KK)
            v = g_kern[((size_t)(b * HH + hc) * WW + wc) * CK + lane * 4 + sh * 2 + sw];
        float m = v;
        #pragma unroll
        for (int off = 16; off; off >>= 1)
            m = fmaxf(m, __shfl_xor_sync(0xffffffffu, m, off));
        float e = (lane < KK) ? __expf(v - m) : 0.f;
        float su = e;
        #pragma unroll
        for (int off = 16; off; off >>= 1)
            su += __shfl_xor_sync(0xffffffffu, su, off);
        if (lane < KK)
            ((float*)&sk[px][lane])[d] = e / su;
    }
    __syncthreads();

    // ---- per-px FMA, results to staging ----
    #pragma unroll
    for (int i = 0; i < 5; i++) {
        const ulonglong2* skp = (const ulonglong2*)&sk[i][0];
        u64 a01 = 0, a23 = 0;
        #pragma unroll
        for (int k = 0; k < 25; k++) {
            u64 xx = dup2f(xw[(k / 5) * 9 + i + (k % 5)]);
            ulonglong2 w = skp[k];
            fma2(a01, xx, w.x);
            fma2(a23, xx, w.y);
        }
        *(u64*)&st[t * ST_STRIDE + i * 4]     = a01;
        *(u64*)&st[t * ST_STRIDE + i * 4 + 2] = a23;
    }
    __syncthreads();

    // ---- coalesced store: thread = (ch, wu-quad), warp covers consecutive wu ----
    const size_t obase = ((size_t)(b * C_IN) * (2 * HH) + hu) * (2 * WW) + pm0 * 4;
    #pragma unroll
    for (int j = 0; j < 5; j++) {
        int f  = t + j * 256;          // 0..1279
        int ch = f / 5, w4 = f % 5;
        float4 v = *(const float4*)&st[ch * ST_STRIDE + w4 * 4];
        *(float4*)&out[obase + (size_t)ch * (4 * HH * WW) + w4 * 4] = v;
    }
}

// ---------------- launch ----------------
extern "C" void kernel_launch(void* const* d_in, const int* in_sizes, int n_in,
                              void* d_out, int out_size) {
    const float* x     = (const float*)d_in[0];
    const float* wcomp = (const float*)d_in[1];
    const float* wenc  = (const float*)d_in[2];
    float* out = (float*)d_out;

    megaA<<<1050, 128>>>(x, wcomp, wenc);
    stageB_encoder<<<320, 128>>>();
    stageC_reassemble<<<640, 256>>>(out);
}